// round 8
// baseline (speedup 1.0000x reference)
#include <cuda_runtime.h>
#include <math_constants.h>
#include <cstdint>

#define S_LEN 1500
#define NPAIR 750
#define BATCHN 2
#define NH 8
#define DM 16
#define DFF 128
#define NROWS (BATCHN * S_LEN)          // 3000
#define XELEMS (NROWS * DM)             // 48000
#define QPB 168                         // queries per block (even)
#define YBLK 9                          // 9*168 >= 1500
#define STAG_LEN 1500                   // floats per stag buffer (6000B)
#define NSTEP2 24                       // ceil(750/32)

// Scratch (no allocations allowed)
__device__ float g_x[XELEMS];
__device__ float g_q[XELEMS];           // [B,H,S,2]
__device__ float g_k[XELEMS];
__device__ float g_v[XELEMS];
__device__ float g_ctx[XELEMS];

typedef unsigned long long u64;

__device__ __forceinline__ uint32_t smem_u32(const void* p) {
    uint32_t a;
    asm("{ .reg .u64 t; cvta.to.shared.u64 t, %1; cvt.u32.u64 %0, t; }"
        : "=r"(a) : "l"(p));
    return a;
}
__device__ __forceinline__ float ex2f(float x) {
    float y;
    asm("ex2.approx.f32 %0, %1;" : "=f"(y) : "f"(x));
    return y;
}
__device__ __forceinline__ u64 pack2(float lo, float hi) {
    u64 r;
    asm("mov.b64 %0, {%1, %2};" : "=l"(r) : "f"(lo), "f"(hi));
    return r;
}
__device__ __forceinline__ void unpack2(float& lo, float& hi, u64 v) {
    asm("mov.b64 {%0, %1}, %2;" : "=f"(lo), "=f"(hi) : "l"(v));
}
__device__ __forceinline__ u64 mulx2(u64 a, u64 b) {
    u64 r;
    asm("mul.rn.f32x2 %0, %1, %2;" : "=l"(r) : "l"(a), "l"(b));
    return r;
}
__device__ __forceinline__ u64 addx2(u64 a, u64 b) {
    u64 r;
    asm("add.rn.f32x2 %0, %1, %2;" : "=l"(r) : "l"(a), "l"(b));
    return r;
}
__device__ __forceinline__ u64 fmax2(u64 a, u64 b, u64 c) {
    u64 r;
    asm("fma.rn.f32x2 %0, %1, %2, %3;" : "=l"(r) : "l"(a), "l"(b), "l"(c));
    return r;
}

// ---------------------------------------------------------------------------
// embed + layer-0 qkv: 32 rows per 512-thread block
__global__ void __launch_bounds__(512) embed_kernel(
    const float* __restrict__ enc, const float* __restrict__ srcw,
    const float* __restrict__ srcb, const float* __restrict__ Wq,
    const float* __restrict__ Wk, const float* __restrict__ Wv)
{
    __shared__ float swq[256], swk[256], swv[256];
    int tid = threadIdx.x;
    if (tid < 256) { swq[tid] = Wq[tid]; swk[tid] = Wk[tid]; swv[tid] = Wv[tid]; }

    int r = tid >> 4, d = tid & 15;
    int grow = blockIdx.x * 32 + r;          // = b*1500 + s
    int lane = tid & 31, base = lane & 16;
    float xv = 0.f;
    if (grow < NROWS) {
        int s = grow % S_LEN;
        const float c = -0.57564627324851148f;   // -ln(10000)/16
        float dv = __expf((float)(d & ~1) * c);
        float ph = (float)s * dv;
        float pe = (d & 1) ? cosf(ph) : sinf(ph);
        xv = enc[grow] * srcw[d] + srcb[d] + pe;
        g_x[grow * DM + d] = xv;
    }
    __syncthreads();

    float xk[16];
#pragma unroll
    for (int k = 0; k < 16; k++) xk[k] = __shfl_sync(0xffffffffu, xv, base + k);
    if (grow < NROWS) {
        float q = 0.f, kk = 0.f, vv = 0.f;
#pragma unroll
        for (int m = 0; m < 16; m++) {
            q  = fmaf(xk[m], swq[m * 16 + d], q);
            kk = fmaf(xk[m], swk[m * 16 + d], kk);
            vv = fmaf(xk[m], swv[m * 16 + d], vv);
        }
        int b = grow / S_LEN, s = grow - b * S_LEN;
        int h = d >> 1, dk = d & 1;
        int o = ((b * NH + h) * S_LEN + s) * 2 + dk;
        g_q[o] = q; g_k[o] = kk; g_v[o] = vv;
    }
}

// ---------------------------------------------------------------------------
// attention: 16 warps/block (1 block/SM), 2 queries/warp/pass, key-pair
// packed SMEM layout enabling f32x2 math, double-buffered TMA row stores.
__global__ void __launch_bounds__(512, 1) attn_kernel(float* __restrict__ attn_out)
{
    extern __shared__ __align__(16) float smem[];
    // skx[j] = (kx[2j], kx[2j+1], ky[2j], ky[2j+1]) as ulonglong2
    ulonglong2* skx = (ulonglong2*)smem;                  // [750] 12000B
    ulonglong2* svv = (ulonglong2*)(smem + 4 * NPAIR);    // [750] 12000B
    float* stagbase = smem + 8 * NPAIR;                   // [16][2][STAG_LEN]

    int bh = blockIdx.x;
    int tid = threadIdx.x;
    const float4* kp4 = (const float4*)(((const float2*)g_k) + bh * S_LEN);
    const float4* vp4 = (const float4*)(((const float2*)g_v) + bh * S_LEN);
    for (int i = tid; i < NPAIR; i += 512) {
        float4 kk2 = kp4[i];   // (k2i.x,k2i.y,k2i+1.x,k2i+1.y)
        float4 vv2 = vp4[i];
        skx[i] = make_ulonglong2(pack2(kk2.x, kk2.z), pack2(kk2.y, kk2.w));
        svv[i] = make_ulonglong2(pack2(vv2.x, vv2.z), pack2(vv2.y, vv2.w));
    }
    __syncthreads();

    int warp = tid >> 5, lane = tid & 31;
    float* stag0 = stagbase + warp * (2 * STAG_LEN);
    float* stag1 = stag0 + STAG_LEN;
    uint32_t sbuf0 = smem_u32(stag0);
    uint32_t sbuf1 = smem_u32(stag1);
    u64* stagq0 = (u64*)stag0;
    u64* stagq1 = (u64*)stag1;
    int b = bh >> 3, h = bh & 7;
    int p0 = (blockIdx.y * QPB) >> 1;
    int pend = min(blockIdx.y * QPB + QPB, S_LEN) >> 1;
    // fold 1/sqrt(dk) and log2(e) into q
    const float qscale = 0.70710678118654752f * 1.44269504088896341f;

    for (int p = p0 + warp; p < pend; p += 16) {
        int qa = 2 * p, qb = 2 * p + 1;
        float2 qva = ((const float2*)g_q)[bh * S_LEN + qa];
        float2 qvb = ((const float2*)g_q)[bh * S_LEN + qb];
        u64 qax = pack2(qva.x * qscale, qva.x * qscale);
        u64 qay = pack2(qva.y * qscale, qva.y * qscale);
        u64 qbx = pack2(qvb.x * qscale, qvb.x * qscale);
        u64 qby = pack2(qvb.y * qscale, qvb.y * qscale);

        u64 ea[NSTEP2], eb[NSTEP2];
        u64 sa2 = 0, sb2 = 0, ca0 = 0, ca1 = 0, cb0 = 0, cb1 = 0;
#pragma unroll
        for (int i = 0; i < NSTEP2; i++) {
            int j = lane + 32 * i;               // key pair index
            if (i < NSTEP2 - 1 || j < NPAIR) {
                ulonglong2 kx = skx[j];          // .x=(kx,kx') .y=(ky,ky')
                ulonglong2 vv = svv[j];          // .x=(vx,vx') .y=(vy,vy')
                u64 sA = fmax2(qax, kx.x, mulx2(qay, kx.y));
                u64 sB = fmax2(qbx, kx.x, mulx2(qby, kx.y));
                float a0, a1, b0, b1;
                unpack2(a0, a1, sA);
                unpack2(b0, b1, sB);
                u64 eA = pack2(ex2f(a0), ex2f(a1));
                u64 eB = pack2(ex2f(b0), ex2f(b1));
                sa2 = addx2(sa2, eA);
                sb2 = addx2(sb2, eB);
                ca0 = fmax2(eA, vv.x, ca0);
                ca1 = fmax2(eA, vv.y, ca1);
                cb0 = fmax2(eB, vv.x, cb0);
                cb1 = fmax2(eB, vv.y, cb1);
                ea[i] = eA; eb[i] = eB;
            }
        }
        float t0, t1;
        unpack2(t0, t1, sa2);  float sa = t0 + t1;
        unpack2(t0, t1, sb2);  float sb = t0 + t1;
        unpack2(t0, t1, ca0);  float a0s = t0 + t1;
        unpack2(t0, t1, ca1);  float a1s = t0 + t1;
        unpack2(t0, t1, cb0);  float b0s = t0 + t1;
        unpack2(t0, t1, cb1);  float b1s = t0 + t1;
#pragma unroll
        for (int o = 16; o; o >>= 1) {
            sa  += __shfl_xor_sync(0xffffffffu, sa,  o);
            sb  += __shfl_xor_sync(0xffffffffu, sb,  o);
            a0s += __shfl_xor_sync(0xffffffffu, a0s, o);
            a1s += __shfl_xor_sync(0xffffffffu, a1s, o);
            b0s += __shfl_xor_sync(0xffffffffu, b0s, o);
            b1s += __shfl_xor_sync(0xffffffffu, b1s, o);
        }
        float ra = 1.0f / sa, rb = 1.0f / sb;
        u64 raa = pack2(ra, ra), rbb = pack2(rb, rb);

        // ---- row A -> stag0 (allow 1 in-flight group on stag1) ----
        if (lane == 0)
            asm volatile("cp.async.bulk.wait_group.read 1;" ::: "memory");
        __syncwarp();
#pragma unroll
        for (int i = 0; i < NSTEP2; i++) {
            int j = lane + 32 * i;
            if (i < NSTEP2 - 1 || j < NPAIR) stagq0[j] = mulx2(ea[i], raa);
        }
        __syncwarp();
        if (lane == 0) {
            asm volatile("fence.proxy.async.shared::cta;" ::: "memory");
            float* gdst = attn_out + ((size_t)bh * S_LEN + qa) * S_LEN;
            asm volatile(
                "cp.async.bulk.global.shared::cta.bulk_group [%0], [%1], %2;"
                :: "l"(gdst), "r"(sbuf0), "r"((uint32_t)(S_LEN * 4)) : "memory");
            asm volatile("cp.async.bulk.commit_group;" ::: "memory");
        }

        // ---- row B -> stag1 ----
        if (lane == 0)
            asm volatile("cp.async.bulk.wait_group.read 1;" ::: "memory");
        __syncwarp();
#pragma unroll
        for (int i = 0; i < NSTEP2; i++) {
            int j = lane + 32 * i;
            if (i < NSTEP2 - 1 || j < NPAIR) stagq1[j] = mulx2(eb[i], rbb);
        }
        __syncwarp();
        if (lane == 0) {
            asm volatile("fence.proxy.async.shared::cta;" ::: "memory");
            float* gdst = attn_out + ((size_t)bh * S_LEN + qb) * S_LEN;
            asm volatile(
                "cp.async.bulk.global.shared::cta.bulk_group [%0], [%1], %2;"
                :: "l"(gdst), "r"(sbuf1), "r"((uint32_t)(S_LEN * 4)) : "memory");
            asm volatile("cp.async.bulk.commit_group;" ::: "memory");

            int basea = (b * S_LEN + qa) * DM + h * 2;
            int baseb = (b * S_LEN + qb) * DM + h * 2;
            g_ctx[basea]     = a0s * ra;
            g_ctx[basea + 1] = a1s * ra;
            g_ctx[baseb]     = b0s * rb;
            g_ctx[baseb + 1] = b1s * rb;
        }
    }
    if (lane == 0)
        asm volatile("cp.async.bulk.wait_group 0;" ::: "memory");
}

// ---------------------------------------------------------------------------
// post: x=LN(ctx@Wo+x); x=LN(relu(x@W1)@W2+x); then next-layer qkv (fused).
__global__ void __launch_bounds__(512) post_kernel(
    const float* __restrict__ Wo, const float* __restrict__ W1,
    const float* __restrict__ W2, const float* __restrict__ Wqn,
    const float* __restrict__ Wkn, const float* __restrict__ Wvn,
    float* __restrict__ outx, int last)
{
    __shared__ float sw1[DM * DFF];
    __shared__ float sw2[DFF * DM];
    __shared__ float swo[256];
    __shared__ float swq[256], swk[256], swv[256];
    __shared__ float sh[32][DFF];

    int tid = threadIdx.x;
    if (tid < 256) swo[tid] = Wo[tid];
    for (int i = tid; i < DM * DFF; i += 512) { sw1[i] = W1[i]; sw2[i] = W2[i]; }
    if (!last && tid < 256) { swq[tid] = Wqn[tid]; swk[tid] = Wkn[tid]; swv[tid] = Wvn[tid]; }

    int r = tid >> 4, d = tid & 15;
    int grow = blockIdx.x * 32 + r;
    int lane = tid & 31, base = lane & 16;
    bool ok = grow < NROWS;
    float xv = ok ? g_x[grow * DM + d]   : 0.f;
    float cv = ok ? g_ctx[grow * DM + d] : 0.f;
    __syncthreads();

    float s1 = xv;
#pragma unroll
    for (int k = 0; k < 16; k++) {
        float ck = __shfl_sync(0xffffffffu, cv, base + k);
        s1 = fmaf(ck, swo[k * 16 + d], s1);
    }

    float mean = s1;
#pragma unroll
    for (int o = 8; o; o >>= 1) mean += __shfl_xor_sync(0xffffffffu, mean, o);
    mean *= (1.0f / 16.0f);
    float dv = s1 - mean;
    float var = dv * dv;
#pragma unroll
    for (int o = 8; o; o >>= 1) var += __shfl_xor_sync(0xffffffffu, var, o);
    var *= (1.0f / 16.0f);
    float t = dv * rsqrtf(var + 1e-5f);

    float tk[16];
#pragma unroll
    for (int k = 0; k < 16; k++) tk[k] = __shfl_sync(0xffffffffu, t, base + k);
#pragma unroll
    for (int i = 0; i < 8; i++) {
        int j = d + 16 * i;
        float hv = 0.f;
#pragma unroll
        for (int k = 0; k < 16; k++) hv = fmaf(tk[k], sw1[k * DFF + j], hv);
        sh[r][j] = fmaxf(hv, 0.f);
    }
    __syncthreads();

    float s2 = t;
#pragma unroll
    for (int j = 0; j < DFF; j++) s2 = fmaf(sh[r][j], sw2[j * 16 + d], s2);

    float mean2 = s2;
#pragma unroll
    for (int o = 8; o; o >>= 1) mean2 += __shfl_xor_sync(0xffffffffu, mean2, o);
    mean2 *= (1.0f / 16.0f);
    float dv2 = s2 - mean2;
    float var2 = dv2 * dv2;
#pragma unroll
    for (int o = 8; o; o >>= 1) var2 += __shfl_xor_sync(0xffffffffu, var2, o);
    var2 *= (1.0f / 16.0f);
    float t2 = dv2 * rsqrtf(var2 + 1e-5f);

    if (last) {
        if (ok) outx[grow * DM + d] = t2;
        return;
    }
    if (ok) g_x[grow * DM + d] = t2;

    float x2k[16];
#pragma unroll
    for (int k = 0; k < 16; k++) x2k[k] = __shfl_sync(0xffffffffu, t2, base + k);
    if (ok) {
        float q = 0.f, kk = 0.f, vv = 0.f;
#pragma unroll
        for (int m = 0; m < 16; m++) {
            q  = fmaf(x2k[m], swq[m * 16 + d], q);
            kk = fmaf(x2k[m], swk[m * 16 + d], kk);
            vv = fmaf(x2k[m], swv[m * 16 + d], vv);
        }
        int b = grow / S_LEN, s = grow - b * S_LEN;
        int h = d >> 1, dk = d & 1;
        int o = ((b * NH + h) * S_LEN + s) * 2 + dk;
        g_q[o] = q; g_k[o] = kk; g_v[o] = vv;
    }
}

// ---------------------------------------------------------------------------
extern "C" void kernel_launch(void* const* d_in, const int* in_sizes, int n_in,
                              void* d_out, int out_size)
{
    const float* enc  = (const float*)d_in[0];
    const float* srcw = (const float*)d_in[1];
    const float* srcb = (const float*)d_in[2];
    const float* Wq   = (const float*)d_in[3];
    const float* Wk   = (const float*)d_in[4];
    const float* Wv   = (const float*)d_in[5];
    const float* Wo   = (const float*)d_in[6];
    const float* W1   = (const float*)d_in[7];
    const float* W2   = (const float*)d_in[8];
    float* out = (float*)d_out;

    const int ATTN_SMEM = (8 * NPAIR + 16 * 2 * STAG_LEN) * (int)sizeof(float); // 216000
    static int configured = 0;
    if (!configured) {
        cudaFuncSetAttribute(attn_kernel,
                             cudaFuncAttributeMaxDynamicSharedMemorySize, ATTN_SMEM);
        configured = 1;
    }

    embed_kernel<<<94, 512>>>(enc, srcw, srcb, Wq, Wk, Wv);
    for (int l = 0; l < 3; l++) {
        attn_kernel<<<dim3(BATCHN * NH, YBLK), 512, ATTN_SMEM>>>(
            out + XELEMS + (size_t)l * (size_t)BATCHN * NH * S_LEN * S_LEN);
        int last = (l == 2);
        post_kernel<<<94, 512>>>(Wo + l * 256, W1 + l * 2048, W2 + l * 2048,
                                 last ? Wq : Wq + (l + 1) * 256,
                                 last ? Wk : Wk + (l + 1) * 256,
                                 last ? Wv : Wv + (l + 1) * 256,
                                 out, last);
    }
}